// round 9
// baseline (speedup 1.0000x reference)
#include <cuda_runtime.h>

// Fixed shapes: B=32, T=1024, D=1024. All GEMM paths are dead code:
// softmax over a singleton axis => every attention weight == 1.0, so
//   context[b,d] = sum_t values[b,t,d],  aw = 1.0,  cov[b,t] = t.
#define BB 32
#define TT 1024
#define DD 1024
#define D4 256                       // float4 per row (4KB rows)
#define NCHUNK 32                    // chunks per batch
#define TC (TT / NCHUNK)             // 32 rows per chunk (128KB contiguous)

// Output layout (98304 floats):
//   [0, B*D)             context       (zeroed by memset node, RED-accumulated)
//   [B*D, B*D+B*T)       attention_weights (all 1.0)
//   [B*D+B*T, end)       coverage (cov[b,t] = t)

// ---------------- Single streaming kernel: partial sums -> REDG -------------
// The proven 6.27 TB/s shape: 1024 slim CTAs, contiguous 128KB per CTA,
// thread-per-float4-column, 8-deep independent load batches, __ldcs read-once.
// Epilogue: 4 reduction atomics per thread straight into the context output
// (no scratch, no second kernel). Order nondeterminism ~1e-6 rel << 1e-3 tol.
__global__ void stage1_kernel(const float4* __restrict__ vals,
                              float* __restrict__ out) {
    const int c   = blockIdx.x;      // 0..31 chunk
    const int b   = blockIdx.y;      // 0..31 batch
    const int tid = threadIdx.x;     // 0..255 (one float4 column)

    const float4* __restrict__ p = vals + ((size_t)b * TT + (size_t)c * TC) * D4 + tid;

    float x = 0.f, y = 0.f, z = 0.f, w = 0.f;
#pragma unroll
    for (int i = 0; i < TC / 8; ++i) {
        float4 v0 = __ldcs(&p[0 * (size_t)D4]);
        float4 v1 = __ldcs(&p[1 * (size_t)D4]);
        float4 v2 = __ldcs(&p[2 * (size_t)D4]);
        float4 v3 = __ldcs(&p[3 * (size_t)D4]);
        float4 v4 = __ldcs(&p[4 * (size_t)D4]);
        float4 v5 = __ldcs(&p[5 * (size_t)D4]);
        float4 v6 = __ldcs(&p[6 * (size_t)D4]);
        float4 v7 = __ldcs(&p[7 * (size_t)D4]);
        p += 8 * (size_t)D4;
        x += v0.x; y += v0.y; z += v0.z; w += v0.w;
        x += v1.x; y += v1.y; z += v1.z; w += v1.w;
        x += v2.x; y += v2.y; z += v2.z; w += v2.w;
        x += v3.x; y += v3.y; z += v3.z; w += v3.w;
        x += v4.x; y += v4.y; z += v4.z; w += v4.w;
        x += v5.x; y += v5.y; z += v5.z; w += v5.w;
        x += v6.x; y += v6.y; z += v6.z; w += v6.w;
        x += v7.x; y += v7.y; z += v7.z; w += v7.w;
    }

    // Context accumulation: REDG (fire-and-forget), 32 arrivals per address
    // spread across the kernel's 21us lifetime -> no serialization.
    float* ctx = out + (size_t)b * DD + (size_t)tid * 4;
    atomicAdd(ctx + 0, x);
    atomicAdd(ctx + 1, y);
    atomicAdd(ctx + 2, z);
    atomicAdd(ctx + 3, w);

    // aw/cov fill: 1024 blocks x 8 float4 per array (hidden in the stream).
    const int blk = b * NCHUNK + c;  // 0..1023
    if (tid < 8) {
        float4* aw4 = reinterpret_cast<float4*>(out + BB * DD);
        aw4[blk * 8 + tid] = make_float4(1.f, 1.f, 1.f, 1.f);
    } else if (tid >= 32 && tid < 40) {
        float4* cov4 = reinterpret_cast<float4*>(out + BB * DD + BB * TT);
        const int q = blk * 8 + (tid - 32);      // float4 index into [B,T]
        const int t0 = (q * 4) & (TT - 1);
        cov4[q] = make_float4((float)t0, (float)(t0 + 1), (float)(t0 + 2), (float)(t0 + 3));
    }
}

extern "C" void kernel_launch(void* const* d_in, const int* in_sizes, int n_in,
                              void* d_out, int out_size) {
    // Inputs: query, values, W1, b1, W2, b2, W3, b3, V, bV
    const float4* values = (const float4*)d_in[1];
    float* out = (float*)d_out;

    // Zero the context region every replay (graph-capturable memset node),
    // so the RED accumulation below always starts from 0.
    cudaMemsetAsync(out, 0, (size_t)BB * DD * sizeof(float), 0);

    dim3 grid1(NCHUNK, BB);                      // 1024 blocks
    stage1_kernel<<<grid1, D4>>>(values, out);
}

// round 10
// speedup vs baseline: 1.0588x; 1.0588x over previous
#include <cuda_runtime.h>

// Fixed shapes: B=32, T=1024, D=1024. All GEMM paths are dead code:
// softmax over a singleton axis => every attention weight == 1.0, so
//   context[b,d] = sum_t values[b,t,d],  aw = 1.0,  cov[b,t] = t.
#define BB 32
#define TT 1024
#define DD 1024
#define D4 256                       // float4 per row (4KB rows)
#define NCHUNK 32                    // chunks per batch
#define TC (TT / NCHUNK)             // 32 rows per chunk (128KB contiguous)

// Output layout (98304 floats):
//   [0, B*D)             context
//   [B*D, B*D+B*T)       attention_weights (all 1.0)
//   [B*D+B*T, end)       coverage (cov[b,t] = t)

__device__ float4 g_partial[BB * NCHUNK * D4];   // 4 MB scratch

// ---------------- Stage 1: streaming partial sums + aw/cov fill -------------
// Proven 6.27 TB/s shape: 1024 slim CTAs, contiguous 128KB per CTA,
// thread-per-float4-column, 8 independent loads in flight, __ldcs read-once.
// Epilogue fires the PDL trigger so finalize launches/ramps during our tail.
__global__ void stage1_kernel(const float4* __restrict__ vals,
                              float* __restrict__ out) {
    const int c   = blockIdx.x;      // 0..31 chunk
    const int b   = blockIdx.y;      // 0..31 batch
    const int tid = threadIdx.x;     // 0..255 (one float4 column)

    const float4* __restrict__ p = vals + ((size_t)b * TT + (size_t)c * TC) * D4 + tid;

    float x = 0.f, y = 0.f, z = 0.f, w = 0.f;
#pragma unroll
    for (int i = 0; i < TC / 8; ++i) {
        float4 v0 = __ldcs(&p[0 * (size_t)D4]);
        float4 v1 = __ldcs(&p[1 * (size_t)D4]);
        float4 v2 = __ldcs(&p[2 * (size_t)D4]);
        float4 v3 = __ldcs(&p[3 * (size_t)D4]);
        float4 v4 = __ldcs(&p[4 * (size_t)D4]);
        float4 v5 = __ldcs(&p[5 * (size_t)D4]);
        float4 v6 = __ldcs(&p[6 * (size_t)D4]);
        float4 v7 = __ldcs(&p[7 * (size_t)D4]);
        p += 8 * (size_t)D4;
        x += v0.x; y += v0.y; z += v0.z; w += v0.w;
        x += v1.x; y += v1.y; z += v1.z; w += v1.w;
        x += v2.x; y += v2.y; z += v2.z; w += v2.w;
        x += v3.x; y += v3.y; z += v3.z; w += v3.w;
        x += v4.x; y += v4.y; z += v4.z; w += v4.w;
        x += v5.x; y += v5.y; z += v5.z; w += v5.w;
        x += v6.x; y += v6.y; z += v6.z; w += v6.w;
        x += v7.x; y += v7.y; z += v7.z; w += v7.w;
    }
    g_partial[(b * NCHUNK + c) * D4 + tid] = make_float4(x, y, z, w);

    // aw/cov fill: 1024 blocks x 8 float4 per array (hidden in the stream).
    const int blk = b * NCHUNK + c;  // 0..1023
    if (tid < 8) {
        float4* aw4 = reinterpret_cast<float4*>(out + BB * DD);
        aw4[blk * 8 + tid] = make_float4(1.f, 1.f, 1.f, 1.f);
    } else if (tid >= 32 && tid < 40) {
        float4* cov4 = reinterpret_cast<float4*>(out + BB * DD + BB * TT);
        const int q = blk * 8 + (tid - 32);      // float4 index into [B,T]
        const int t0 = (q * 4) & (TT - 1);
        cov4[q] = make_float4((float)t0, (float)(t0 + 1), (float)(t0 + 2), (float)(t0 + 3));
    }

    // PDL trigger: let the dependent finalize grid begin launching/ramping now.
    // Memory visibility is NOT implied by the trigger — finalize's
    // cudaGridDependencySynchronize() waits for this grid's completion.
    cudaTriggerProgrammaticLaunchCompletion();
}

// ---------------- Stage 2: context reduce (PDL-overlapped) ------------------
// R8 shape: 1024 blocks x 256 threads, ONE __ldcg float4 load per thread
// (entire 4.2MB scratch in flight at once), 5-step smem tree over the 32
// chunk-lanes (fixed order, deterministic). With PDL the launch/ramp overlaps
// stage-1's tail; only the ~1us of real work remains on the critical path.
__global__ __launch_bounds__(256) void finalize_kernel(float* __restrict__ out) {
    // Block until stage1's grid has completed and its writes are visible.
    cudaGridDependencySynchronize();

    const int ds = blockIdx.x;       // 0..31 d-slice
    const int b  = blockIdx.y;       // 0..31 batch
    const int tid  = threadIdx.x;
    const int col  = tid & 7;        // 0..7
    const int lane = tid >> 3;       // 0..31 (chunk index)

    const int d4 = ds * 8 + col;
    float4 v = __ldcg(&g_partial[((size_t)b * NCHUNK + lane) * D4 + d4]);

    __shared__ float4 red[32][8];
    red[lane][col] = v;
    __syncthreads();

#pragma unroll
    for (int s = 16; s > 0; s >>= 1) {
        if (lane < s) {
            float4 a = red[lane][col];
            float4 c2 = red[lane + s][col];
            red[lane][col] = make_float4(a.x + c2.x, a.y + c2.y, a.z + c2.z, a.w + c2.w);
        }
        __syncthreads();
    }

    if (tid < 8) {
        reinterpret_cast<float4*>(out)[(size_t)b * D4 + ds * 8 + tid] = red[0][tid];
    }
}

extern "C" void kernel_launch(void* const* d_in, const int* in_sizes, int n_in,
                              void* d_out, int out_size) {
    // Inputs: query, values, W1, b1, W2, b2, W3, b3, V, bV
    const float4* values = (const float4*)d_in[1];
    float* out = (float*)d_out;

    dim3 grid1(NCHUNK, BB);                      // 1024 blocks
    stage1_kernel<<<grid1, D4>>>(values, out);

    // Finalize with programmatic dependent launch: its launch + CTA ramp
    // overlaps stage1's tail; gridsync inside provides the data dependency.
    cudaLaunchConfig_t cfg = {};
    cfg.gridDim = dim3(32, BB);                  // 1024 blocks
    cfg.blockDim = dim3(256);
    cfg.dynamicSmemBytes = 0;
    cfg.stream = 0;
    cudaLaunchAttribute attr[1];
    attr[0].id = cudaLaunchAttributeProgrammaticStreamSerialization;
    attr[0].val.programmaticStreamSerializationAllowed = 1;
    cfg.attrs = attr;
    cfg.numAttrs = 1;
    cudaLaunchKernelEx(&cfg, finalize_kernel, out);
}

// round 11
// speedup vs baseline: 1.0749x; 1.0152x over previous
#include <cuda_runtime.h>
#include <cstdint>

// Fixed shapes: B=32, T=1024, D=1024. All GEMM paths are dead code:
// softmax over a singleton axis => every attention weight == 1.0, so
//   context[b,d] = sum_t values[b,t,d],  aw = 1.0,  cov[b,t] = t.
#define BB 32
#define TT 1024
#define DD 1024
#define D4 256                       // float4 per row (4KB rows)
#define NCHUNK 32                    // chunks per batch
#define TC (TT / NCHUNK)             // 32 rows per chunk (128KB contiguous)

// Output layout (98304 floats):
//   [0, B*D)             context   (zeroed by memset node, TMA-bulk-reduced)
//   [B*D, B*D+B*T)       attention_weights (all 1.0)
//   [B*D+B*T, end)       coverage (cov[b,t] = t)

__device__ __forceinline__ uint32_t smem_u32(const void* p) {
    uint32_t a;
    asm("{ .reg .u64 t; cvta.to.shared.u64 t, %1; cvt.u32.u64 %0, t; }"
        : "=r"(a) : "l"(p));
    return a;
}

// ---------------- Single kernel: stream + TMA bulk-reduce epilogue ----------
// Proven 6.27 TB/s shape: 1024 slim CTAs, contiguous 128KB per CTA,
// thread-per-float4-column, 8 independent loads in flight, __ldcs read-once.
// Epilogue: CTA partial (4KB) lands in SMEM; ONE cp.reduce.async.bulk adds it
// into the context row in global memory. 1024 bulk ops total, 32B-sector
// reduce granularity at the LTS (8x fewer ops than scalar REDG) -> hidden.
__global__ void stage1_kernel(const float4* __restrict__ vals,
                              float* __restrict__ out) {
    __shared__ float4 part[D4];      // 4KB partial for this (b, chunk)

    const int c   = blockIdx.x;      // 0..31 chunk
    const int b   = blockIdx.y;      // 0..31 batch
    const int tid = threadIdx.x;     // 0..255 (one float4 column)

    const float4* __restrict__ p = vals + ((size_t)b * TT + (size_t)c * TC) * D4 + tid;

    float x = 0.f, y = 0.f, z = 0.f, w = 0.f;
#pragma unroll
    for (int i = 0; i < TC / 8; ++i) {
        float4 v0 = __ldcs(&p[0 * (size_t)D4]);
        float4 v1 = __ldcs(&p[1 * (size_t)D4]);
        float4 v2 = __ldcs(&p[2 * (size_t)D4]);
        float4 v3 = __ldcs(&p[3 * (size_t)D4]);
        float4 v4 = __ldcs(&p[4 * (size_t)D4]);
        float4 v5 = __ldcs(&p[5 * (size_t)D4]);
        float4 v6 = __ldcs(&p[6 * (size_t)D4]);
        float4 v7 = __ldcs(&p[7 * (size_t)D4]);
        p += 8 * (size_t)D4;
        x += v0.x; y += v0.y; z += v0.z; w += v0.w;
        x += v1.x; y += v1.y; z += v1.z; w += v1.w;
        x += v2.x; y += v2.y; z += v2.z; w += v2.w;
        x += v3.x; y += v3.y; z += v3.z; w += v3.w;
        x += v4.x; y += v4.y; z += v4.z; w += v4.w;
        x += v5.x; y += v5.y; z += v5.z; w += v5.w;
        x += v6.x; y += v6.y; z += v6.z; w += v6.w;
        x += v7.x; y += v7.y; z += v7.z; w += v7.w;
    }
    part[tid] = make_float4(x, y, z, w);

    // aw/cov fill: 1024 blocks x 8 float4 per array (hidden in the stream).
    const int blk = b * NCHUNK + c;  // 0..1023
    if (tid < 8) {
        float4* aw4 = reinterpret_cast<float4*>(out + BB * DD);
        aw4[blk * 8 + tid] = make_float4(1.f, 1.f, 1.f, 1.f);
    } else if (tid >= 32 && tid < 40) {
        float4* cov4 = reinterpret_cast<float4*>(out + BB * DD + BB * TT);
        const int q = blk * 8 + (tid - 32);      // float4 index into [B,T]
        const int t0 = (q * 4) & (TT - 1);
        cov4[q] = make_float4((float)t0, (float)(t0 + 1), (float)(t0 + 2), (float)(t0 + 3));
    }

    __syncthreads();                 // partial complete in SMEM

    if (tid == 0) {
        // Order generic SMEM stores before the async-proxy TMA read.
        asm volatile("fence.proxy.async.shared::cta;" ::: "memory");
        float* dst = out + (size_t)b * DD;       // context row for this batch
        uint32_t src = smem_u32(part);
        asm volatile(
            "cp.reduce.async.bulk.global.shared::cta.bulk_group.add.f32 "
            "[%0], [%1], %2;"
            :: "l"(dst), "r"(src), "r"((uint32_t)(D4 * sizeof(float4)))
            : "memory");
        asm volatile("cp.async.bulk.commit_group;" ::: "memory");
        asm volatile("cp.async.bulk.wait_group 0;" ::: "memory");
    }
}

extern "C" void kernel_launch(void* const* d_in, const int* in_sizes, int n_in,
                              void* d_out, int out_size) {
    // Inputs: query, values, W1, b1, W2, b2, W3, b3, V, bV
    const float4* values = (const float4*)d_in[1];
    float* out = (float*)d_out;

    // Zero the context region every replay so the bulk-reduce accumulation
    // restarts from 0 (graph-capturable memset node).
    cudaMemsetAsync(out, 0, (size_t)BB * DD * sizeof(float), 0);

    dim3 grid1(NCHUNK, BB);                      // 1024 blocks
    stage1_kernel<<<grid1, D4>>>(values, out);
}

// round 12
// speedup vs baseline: 1.1662x; 1.0850x over previous
#include <cuda_runtime.h>
#include <cstdint>

// Fixed shapes: B=32, T=1024, D=1024. All GEMM paths are dead code:
// softmax over a singleton axis => every attention weight == 1.0, so
//   context[b,d] = sum_t values[b,t,d],  aw = 1.0,  cov[b,t] = t.
#define BB 32
#define TT 1024
#define DD 1024
#define D4 256                       // float4 per row (4KB rows)
#define NCHUNK 32                    // chunks per batch
#define TC (TT / NCHUNK)             // 32 rows per chunk (128KB contiguous)

// Output layout (98304 floats):
//   [0, B*D)             context   (zeroed in-grid, TMA-bulk-reduce accumulated)
//   [B*D, B*D+B*T)       attention_weights (all 1.0)
//   [B*D+B*T, end)       coverage (cov[b,t] = t)

// Per-batch monotonic tickets (zero-init once at module load; epoch arithmetic
// makes them replay-safe without ever resetting). Stride 32 -> one per 128B.
__device__ unsigned int g_cnt[BB * 32];

__device__ __forceinline__ uint32_t smem_u32(const void* p) {
    uint32_t a;
    asm("{ .reg .u64 t; cvta.to.shared.u64 t, %1; cvt.u32.u64 %0, t; }"
        : "=r"(a) : "l"(p));
    return a;
}

// --------- Single kernel: in-grid zero + stream + TMA bulk-reduce -----------
// Proven stream shape: 1024 slim CTAs, contiguous 128KB per CTA,
// thread-per-float4-column, 8 independent __ldcs loads in flight.
// Zero-init handshake at t~0; bulk-reduce epilogue at t~20us (check is a
// single satisfied load by then, not a spin).
__global__ __launch_bounds__(256) void stage1_kernel(const float4* __restrict__ vals,
                                                     float* __restrict__ out) {
    __shared__ float4 part[D4];      // 4KB partial for this (b, chunk)

    const int c   = blockIdx.x;      // 0..31 chunk
    const int b   = blockIdx.y;      // 0..31 batch
    const int tid = threadIdx.x;     // 0..255 (one float4 column)

    // ---- Prologue: zero this CTA's 128B share of context, take a ticket ----
    // Batch b's context row [b*DD, b*DD+DD) is split across its 32 CTAs.
    if (tid < 8) {
        float4* z = reinterpret_cast<float4*>(out + (size_t)b * DD + (size_t)c * 32);
        z[tid] = make_float4(0.f, 0.f, 0.f, 0.f);
        __threadfence();             // zeros visible before our ticket
    }
    __syncthreads();
    __shared__ unsigned int s_ticket;
    if (tid == 0) s_ticket = atomicAdd(&g_cnt[b * 32], 1u);

    // ---- Stream: contiguous 128KB, 8-deep independent loads ----
    const float4* __restrict__ p = vals + ((size_t)b * TT + (size_t)c * TC) * D4 + tid;

    float x = 0.f, y = 0.f, z = 0.f, w = 0.f;
#pragma unroll
    for (int i = 0; i < TC / 8; ++i) {
        float4 v0 = __ldcs(&p[0 * (size_t)D4]);
        float4 v1 = __ldcs(&p[1 * (size_t)D4]);
        float4 v2 = __ldcs(&p[2 * (size_t)D4]);
        float4 v3 = __ldcs(&p[3 * (size_t)D4]);
        float4 v4 = __ldcs(&p[4 * (size_t)D4]);
        float4 v5 = __ldcs(&p[5 * (size_t)D4]);
        float4 v6 = __ldcs(&p[6 * (size_t)D4]);
        float4 v7 = __ldcs(&p[7 * (size_t)D4]);
        p += 8 * (size_t)D4;
        x += v0.x; y += v0.y; z += v0.z; w += v0.w;
        x += v1.x; y += v1.y; z += v1.z; w += v1.w;
        x += v2.x; y += v2.y; z += v2.z; w += v2.w;
        x += v3.x; y += v3.y; z += v3.z; w += v3.w;
        x += v4.x; y += v4.y; z += v4.z; w += v4.w;
        x += v5.x; y += v5.y; z += v5.z; w += v5.w;
        x += v6.x; y += v6.y; z += v6.z; w += v6.w;
        x += v7.x; y += v7.y; z += v7.z; w += v7.w;
    }
    part[tid] = make_float4(x, y, z, w);

    // aw/cov fill: 1024 blocks x 8 float4 per array (hidden in the stream).
    const int blk = b * NCHUNK + c;  // 0..1023
    if (tid >= 64 && tid < 72) {
        float4* aw4 = reinterpret_cast<float4*>(out + BB * DD);
        aw4[blk * 8 + (tid - 64)] = make_float4(1.f, 1.f, 1.f, 1.f);
    } else if (tid >= 96 && tid < 104) {
        float4* cov4 = reinterpret_cast<float4*>(out + BB * DD + BB * TT);
        const int q = blk * 8 + (tid - 96);      // float4 index into [B,T]
        const int t0 = (q * 4) & (TT - 1);
        cov4[q] = make_float4((float)t0, (float)(t0 + 1), (float)(t0 + 2), (float)(t0 + 3));
    }

    __syncthreads();                 // partial complete in SMEM; s_ticket visible

    if (tid == 0) {
        // Wait until all 32 CTAs of this batch (this replay's epoch) have
        // zeroed their context share. By now (~20us in) this is a single
        // satisfied load. Epoch arithmetic keeps it replay-safe.
        const unsigned int target = (s_ticket / NCHUNK + 1u) * NCHUNK;
        while (*(volatile unsigned int*)&g_cnt[b * 32] < target) {}
        __threadfence();             // acquire: peer zeros visible
        // Order generic stores (smem partial + global zeros) before async proxy.
        asm volatile("fence.proxy.async;" ::: "memory");

        float* dst = out + (size_t)b * DD;       // context row for this batch
        uint32_t src = smem_u32(part);
        asm volatile(
            "cp.reduce.async.bulk.global.shared::cta.bulk_group.add.f32 "
            "[%0], [%1], %2;"
            :: "l"(dst), "r"(src), "r"((uint32_t)(D4 * sizeof(float4)))
            : "memory");
        asm volatile("cp.async.bulk.commit_group;" ::: "memory");
        asm volatile("cp.async.bulk.wait_group 0;" ::: "memory");
    }
}

extern "C" void kernel_launch(void* const* d_in, const int* in_sizes, int n_in,
                              void* d_out, int out_size) {
    // Inputs: query, values, W1, b1, W2, b2, W3, b3, V, bV
    const float4* values = (const float4*)d_in[1];
    float* out = (float*)d_out;

    dim3 grid1(NCHUNK, BB);                      // 1024 blocks, one wave
    stage1_kernel<<<grid1, D4>>>(values, out);
}